// round 3
// baseline (speedup 1.0000x reference)
#include <cuda_runtime.h>
#include <cuda_bf16.h>

// Problem constants
#define B_SZ   16
#define N_SZ   4
#define H_SZ   32
#define W_SZ   32
#define DIM    1024
#define FPN    512
#define NOUT   2048                       // 4 * FPN
#define MROWS  (B_SZ * N_SZ * H_SZ * W_SZ) // 65536

// GEMM tiling
#define BM   128
#define BN   128
#define BK   16
#define SPAD 132   // padded shared row length (floats) to reduce staging conflicts

// ---------------------------------------------------------------------------
// Scratch (device globals; no dynamic allocation allowed)
// ---------------------------------------------------------------------------
__device__ float g_scale[MROWS];      // rstd per row
__device__ float g_shift[MROWS];      // rstd * mu per row
__device__ float g_Wp[NOUT * DIM];    // W'[o,c] = gamma[c] * W[o,c]  (8 MB)
__device__ float g_s1[NOUT];          // sum_c W'[o,c]
__device__ float g_s2[NOUT];          // sum_c beta[c]*W[o,c] + b[o]

// ---------------------------------------------------------------------------
// Kernel A: per-row LayerNorm statistics (one warp per row)
// ---------------------------------------------------------------------------
__global__ void ln_stats_kernel(const float* __restrict__ x) {
    int gw   = (blockIdx.x * blockDim.x + threadIdx.x) >> 5;
    int lane = threadIdx.x & 31;
    if (gw >= MROWS) return;
    const float4* row = reinterpret_cast<const float4*>(x) + (size_t)gw * (DIM / 4);

    float4 v[8];
    float s = 0.f;
#pragma unroll
    for (int i = 0; i < 8; i++) {
        v[i] = row[lane + i * 32];
        s += v[i].x + v[i].y + v[i].z + v[i].w;
    }
#pragma unroll
    for (int o = 16; o > 0; o >>= 1) s += __shfl_xor_sync(0xffffffffu, s, o);
    float mu = s * (1.f / DIM);

    float q = 0.f;
#pragma unroll
    for (int i = 0; i < 8; i++) {
        float a = v[i].x - mu, b = v[i].y - mu, c = v[i].z - mu, d = v[i].w - mu;
        q += a * a + b * b + c * c + d * d;
    }
#pragma unroll
    for (int o = 16; o > 0; o >>= 1) q += __shfl_xor_sync(0xffffffffu, q, o);

    if (lane == 0) {
        float rstd = rsqrtf(q * (1.f / DIM) + 1e-5f);
        g_scale[gw] = rstd;
        g_shift[gw] = rstd * mu;
    }
}

// ---------------------------------------------------------------------------
// Kernel B: fold gamma into W, precompute per-output affine terms
// (one warp per output row o)
// ---------------------------------------------------------------------------
__global__ void prep_w_kernel(const float* __restrict__ Wm,
                              const float* __restrict__ gamma,
                              const float* __restrict__ beta,
                              const float* __restrict__ bias) {
    int o    = (blockIdx.x * blockDim.x + threadIdx.x) >> 5;
    int lane = threadIdx.x & 31;
    if (o >= NOUT) return;

    const float4* wr = reinterpret_cast<const float4*>(Wm) + (size_t)o * (DIM / 4);
    const float4* g4 = reinterpret_cast<const float4*>(gamma);
    const float4* b4 = reinterpret_cast<const float4*>(beta);
    float4* outp = reinterpret_cast<float4*>(g_Wp) + (size_t)o * (DIM / 4);

    float s1 = 0.f, s2 = 0.f;
#pragma unroll
    for (int i = 0; i < 8; i++) {
        int c = lane + i * 32;
        float4 wv = wr[c], gv = g4[c], bv = b4[c];
        float4 ov;
        ov.x = wv.x * gv.x; ov.y = wv.y * gv.y;
        ov.z = wv.z * gv.z; ov.w = wv.w * gv.w;
        s1 += ov.x + ov.y + ov.z + ov.w;
        s2 += wv.x * bv.x + wv.y * bv.y + wv.z * bv.z + wv.w * bv.w;
        outp[c] = ov;
    }
#pragma unroll
    for (int d = 16; d > 0; d >>= 1) {
        s1 += __shfl_xor_sync(0xffffffffu, s1, d);
        s2 += __shfl_xor_sync(0xffffffffu, s2, d);
    }
    if (lane == 0) {
        g_s1[o] = s1;
        g_s2[o] = s2 + bias[o];
    }
}

// ---------------------------------------------------------------------------
// Kernel C: GEMM (x @ W'^T) + LN-affine + patch-split scatter epilogue
// 128x128 tile, BK=16, 256 threads, 8x8 per-thread micro-tile, double-buffered
// ---------------------------------------------------------------------------
__global__ void __launch_bounds__(256, 2)
gemm_kernel(const float* __restrict__ A, float* __restrict__ out) {
    __shared__ __align__(16) float As[2][BK][SPAD];
    __shared__ __align__(16) float Bs[2][BK][SPAD];

    const int tid = threadIdx.x;
    const int tx  = tid & 15;   // 16 col-threads
    const int ty  = tid >> 4;   // 16 row-threads
    const int R0  = blockIdx.y * BM;
    const int C0  = blockIdx.x * BN;

    // staging: each thread loads 4 float4s (2 A rows + 2 B rows) per stage
    const int lr = tid >> 2;          // 0..63
    const int lc = (tid & 3) << 2;    // 0,4,8,12
    const float* Ap = A    + (size_t)(R0 + lr) * DIM + lc;
    const float* Bp = g_Wp + (size_t)(C0 + lr) * DIM + lc;

    float acc[8][8];
#pragma unroll
    for (int i = 0; i < 8; i++)
#pragma unroll
        for (int j = 0; j < 8; j++) acc[i][j] = 0.f;

    // prologue: stage 0
    float4 pa0 = *reinterpret_cast<const float4*>(Ap);
    float4 pa1 = *reinterpret_cast<const float4*>(Ap + 64 * DIM);
    float4 pb0 = *reinterpret_cast<const float4*>(Bp);
    float4 pb1 = *reinterpret_cast<const float4*>(Bp + 64 * DIM);
#pragma unroll
    for (int j = 0; j < 4; j++) {
        As[0][lc + j][lr]      = (&pa0.x)[j];
        As[0][lc + j][lr + 64] = (&pa1.x)[j];
        Bs[0][lc + j][lr]      = (&pb0.x)[j];
        Bs[0][lc + j][lr + 64] = (&pb1.x)[j];
    }
    __syncthreads();

    int buf = 0;
    const int NS = DIM / BK;  // 64 stages
    for (int s = 0; s < NS; s++) {
        if (s + 1 < NS) {   // prefetch next stage into registers (overlaps compute)
            const float* Ap2 = Ap + (s + 1) * BK;
            const float* Bp2 = Bp + (s + 1) * BK;
            pa0 = *reinterpret_cast<const float4*>(Ap2);
            pa1 = *reinterpret_cast<const float4*>(Ap2 + 64 * DIM);
            pb0 = *reinterpret_cast<const float4*>(Bp2);
            pb1 = *reinterpret_cast<const float4*>(Bp2 + 64 * DIM);
        }
#pragma unroll
        for (int k = 0; k < BK; k++) {
            float4 a0 = *reinterpret_cast<const float4*>(&As[buf][k][ty * 4]);
            float4 a1 = *reinterpret_cast<const float4*>(&As[buf][k][ty * 4 + 64]);
            float4 b0 = *reinterpret_cast<const float4*>(&Bs[buf][k][tx * 4]);
            float4 b1 = *reinterpret_cast<const float4*>(&Bs[buf][k][tx * 4 + 64]);
            float am[8] = {a0.x, a0.y, a0.z, a0.w, a1.x, a1.y, a1.z, a1.w};
            float bm[8] = {b0.x, b0.y, b0.z, b0.w, b1.x, b1.y, b1.z, b1.w};
#pragma unroll
            for (int i = 0; i < 8; i++)
#pragma unroll
                for (int j = 0; j < 8; j++)
                    acc[i][j] += am[i] * bm[j];
        }
        if (s + 1 < NS) {
            int nb = buf ^ 1;   // writing the other buffer: safe while buf is read
#pragma unroll
            for (int j = 0; j < 4; j++) {
                As[nb][lc + j][lr]      = (&pa0.x)[j];
                As[nb][lc + j][lr + 64] = (&pa1.x)[j];
                Bs[nb][lc + j][lr]      = (&pb0.x)[j];
                Bs[nb][lc + j][lr + 64] = (&pb1.x)[j];
            }
            __syncthreads();
            buf = nb;
        }
    }

    // ---- Epilogue: y = rstd*acc - (rstd*mu)*s1[o] + s2[o], patch-split store.
    // Within this 128-col tile the quadrant q = o>>9 is constant.
    const int q     = C0 >> 9;
    const int e1    = q >> 1;       // patch row offset
    const int e2    = q & 1;        // patch col offset
    const int fbase = C0 & (FPN - 1);

    float s1v[8], s2v[8];
#pragma unroll
    for (int j = 0; j < 8; j++) {
        int nl = (j < 4) ? (tx * 4 + j) : (64 + tx * 4 + j - 4);
        s1v[j] = g_s1[C0 + nl];
        s2v[j] = g_s2[C0 + nl];
    }

#pragma unroll
    for (int i = 0; i < 8; i++) {
        int ml = (i < 4) ? (ty * 4 + i) : (64 + ty * 4 + i - 4);
        int gr = R0 + ml;
        float sc = g_scale[gr];
        float sh = g_shift[gr];
        int bn = gr >> 10;          // flattened (b,n) in [0,64)
        int h  = (gr >> 5) & 31;
        int w  = gr & 31;
        // out layout: (B, N, 2H, 2W, FPN); row' = 2h+e1, col' = 2w+e2
        size_t obase = (((size_t)(bn * 64 + 2 * h + e1) * 64) + (2 * w + e2)) * FPN + fbase;

        float4 v0, v1;
        v0.x = sc * acc[i][0] - sh * s1v[0] + s2v[0];
        v0.y = sc * acc[i][1] - sh * s1v[1] + s2v[1];
        v0.z = sc * acc[i][2] - sh * s1v[2] + s2v[2];
        v0.w = sc * acc[i][3] - sh * s1v[3] + s2v[3];
        v1.x = sc * acc[i][4] - sh * s1v[4] + s2v[4];
        v1.y = sc * acc[i][5] - sh * s1v[5] + s2v[5];
        v1.z = sc * acc[i][6] - sh * s1v[6] + s2v[6];
        v1.w = sc * acc[i][7] - sh * s1v[7] + s2v[7];
        *reinterpret_cast<float4*>(out + obase + tx * 4)      = v0;
        *reinterpret_cast<float4*>(out + obase + 64 + tx * 4) = v1;
    }
}

// ---------------------------------------------------------------------------
// Launch contract
// ---------------------------------------------------------------------------
extern "C" void kernel_launch(void* const* d_in, const int* in_sizes, int n_in,
                              void* d_out, int out_size) {
    const float* x     = (const float*)d_in[0];  // (16,4,32,32,1024)
    const float* gamma = (const float*)d_in[1];  // (1024,)
    const float* beta  = (const float*)d_in[2];  // (1024,)
    const float* Wm    = (const float*)d_in[3];  // (2048,1024)
    const float* bias  = (const float*)d_in[4];  // (2048,)
    float* out = (float*)d_out;                  // (16,4,64,64,512)

    ln_stats_kernel<<<MROWS / 8, 256>>>(x);
    prep_w_kernel<<<NOUT / 8, 256>>>(Wm, gamma, beta, bias);

    dim3 grid(NOUT / BN, MROWS / BM);  // (16, 512)
    gemm_kernel<<<grid, 256>>>(x, out);
}

// round 5
// speedup vs baseline: 1.6143x; 1.6143x over previous
#include <cuda_runtime.h>
#include <cuda_bf16.h>
#include <cstdint>

// ---------------------------------------------------------------------------
// Problem constants
// ---------------------------------------------------------------------------
#define DIM    1024
#define FPN    512
#define NOUT   2048
#define MROWS  65536            // 16*4*32*32

// GEMM tiling
#define TM 128
#define TN 128
#define BK 32
#define NCHUNK (DIM / BK)       // 32
#define STAGES 4

// SMEM: padded rows of 80B (32 bf16 = 64B data + 16B pad) -> conflict-free ldmatrix
#define ROWB 80
#define ARRB (128 * ROWB)       // 10240 bytes per array per stage
#define OFF_AH 0
#define OFF_AL (1 * ARRB)
#define OFF_BH (2 * ARRB)
#define OFF_BL (3 * ARRB)
#define STAGE_BYTES (4 * ARRB)  // 40960
#define SMEM_TOTAL (STAGES * STAGE_BYTES)  // 163840

// ---------------------------------------------------------------------------
// Device scratch (device globals; no dynamic allocation allowed)
// ---------------------------------------------------------------------------
__device__ float g_scale[MROWS];                      // rstd
__device__ float g_shift[MROWS];                      // rstd * mu
__device__ __nv_bfloat16 g_Ahi[(size_t)MROWS * DIM];  // 128 MB
__device__ __nv_bfloat16 g_Alo[(size_t)MROWS * DIM];  // 128 MB
__device__ __nv_bfloat16 g_Bhi[(size_t)NOUT * DIM];
__device__ __nv_bfloat16 g_Blo[(size_t)NOUT * DIM];
__device__ float g_s1[NOUT];
__device__ float g_s2[NOUT];

// ---------------------------------------------------------------------------
// PTX helpers (all base-PTX, family-generic sm_103 safe)
// ---------------------------------------------------------------------------
__device__ __forceinline__ uint32_t smem_u32(const void* p) {
    uint32_t a;
    asm("{ .reg .u64 t; cvta.to.shared.u64 t, %1; cvt.u32.u64 %0, t; }"
        : "=r"(a) : "l"(p));
    return a;
}
__device__ __forceinline__ void cpasync16(uint32_t dst, const void* src) {
    asm volatile("cp.async.cg.shared.global [%0], [%1], 16;"
                 :: "r"(dst), "l"(src));
}
__device__ __forceinline__ void cp_commit() {
    asm volatile("cp.async.commit_group;");
}
__device__ __forceinline__ void cp_wait3() {
    asm volatile("cp.async.wait_group 3;");
}
__device__ __forceinline__ void ldx4(uint32_t* r, uint32_t addr) {
    asm volatile("ldmatrix.sync.aligned.m8n8.x4.shared.b16 {%0,%1,%2,%3}, [%4];"
                 : "=r"(r[0]), "=r"(r[1]), "=r"(r[2]), "=r"(r[3]) : "r"(addr));
}
__device__ __forceinline__ void mma16816(float* d, const uint32_t* a,
                                         const uint32_t* b) {
    asm volatile(
        "mma.sync.aligned.m16n8k16.row.col.f32.bf16.bf16.f32 "
        "{%0,%1,%2,%3}, {%4,%5,%6,%7}, {%8,%9}, {%0,%1,%2,%3};"
        : "+f"(d[0]), "+f"(d[1]), "+f"(d[2]), "+f"(d[3])
        : "r"(a[0]), "r"(a[1]), "r"(a[2]), "r"(a[3]), "r"(b[0]), "r"(b[1]));
}

// ---------------------------------------------------------------------------
// Kernel A: LN stats + fp32 -> bf16 hi/lo conversion of x (one warp per row)
// ---------------------------------------------------------------------------
__global__ void ln_prep_a_kernel(const float* __restrict__ x) {
    int gw   = (blockIdx.x * blockDim.x + threadIdx.x) >> 5;
    int lane = threadIdx.x & 31;
    const float4* row = reinterpret_cast<const float4*>(x) + (size_t)gw * (DIM / 4);

    float4 v[8];
    float s = 0.f;
#pragma unroll
    for (int i = 0; i < 8; i++) {
        v[i] = row[lane + i * 32];
        s += v[i].x + v[i].y + v[i].z + v[i].w;
    }
#pragma unroll
    for (int o = 16; o > 0; o >>= 1) s += __shfl_xor_sync(0xffffffffu, s, o);
    float mu = s * (1.f / DIM);

    float q = 0.f;
#pragma unroll
    for (int i = 0; i < 8; i++) {
        float a = v[i].x - mu, b = v[i].y - mu, c = v[i].z - mu, d = v[i].w - mu;
        q += a * a + b * b + c * c + d * d;
    }
#pragma unroll
    for (int o = 16; o > 0; o >>= 1) q += __shfl_xor_sync(0xffffffffu, q, o);

    if (lane == 0) {
        float rstd = rsqrtf(q * (1.f / DIM) + 1e-5f);
        g_scale[gw] = rstd;
        g_shift[gw] = rstd * mu;
    }

    // convert raw x to bf16 hi/lo
    uint2* hdst = reinterpret_cast<uint2*>(g_Ahi + (size_t)gw * DIM);
    uint2* ldst = reinterpret_cast<uint2*>(g_Alo + (size_t)gw * DIM);
#pragma unroll
    for (int i = 0; i < 8; i++) {
        int idx = lane + i * 32;
        float f0 = v[i].x, f1 = v[i].y, f2 = v[i].z, f3 = v[i].w;
        __nv_bfloat162 h01 = __floats2bfloat162_rn(f0, f1);
        __nv_bfloat162 h23 = __floats2bfloat162_rn(f2, f3);
        float2 hf01 = __bfloat1622float2(h01);
        float2 hf23 = __bfloat1622float2(h23);
        __nv_bfloat162 l01 = __floats2bfloat162_rn(f0 - hf01.x, f1 - hf01.y);
        __nv_bfloat162 l23 = __floats2bfloat162_rn(f2 - hf23.x, f3 - hf23.y);
        hdst[idx] = make_uint2(*reinterpret_cast<uint32_t*>(&h01),
                               *reinterpret_cast<uint32_t*>(&h23));
        ldst[idx] = make_uint2(*reinterpret_cast<uint32_t*>(&l01),
                               *reinterpret_cast<uint32_t*>(&l23));
    }
}

// ---------------------------------------------------------------------------
// Kernel B: W' = gamma*W as bf16 hi/lo; s1 = sum W', s2 = beta.W + bias
// ---------------------------------------------------------------------------
__global__ void prep_w_kernel(const float* __restrict__ Wm,
                              const float* __restrict__ gamma,
                              const float* __restrict__ beta,
                              const float* __restrict__ bias) {
    int o    = (blockIdx.x * blockDim.x + threadIdx.x) >> 5;
    int lane = threadIdx.x & 31;
    if (o >= NOUT) return;

    const float4* wr = reinterpret_cast<const float4*>(Wm) + (size_t)o * (DIM / 4);
    const float4* g4 = reinterpret_cast<const float4*>(gamma);
    const float4* b4 = reinterpret_cast<const float4*>(beta);
    uint2* hdst = reinterpret_cast<uint2*>(g_Bhi + (size_t)o * DIM);
    uint2* ldst = reinterpret_cast<uint2*>(g_Blo + (size_t)o * DIM);

    float s1 = 0.f, s2 = 0.f;
#pragma unroll
    for (int i = 0; i < 8; i++) {
        int c = lane + i * 32;
        float4 wv = wr[c], gv = g4[c], bv = b4[c];
        float v0 = wv.x * gv.x, v1 = wv.y * gv.y, v2 = wv.z * gv.z, v3 = wv.w * gv.w;
        s1 += v0 + v1 + v2 + v3;
        s2 += wv.x * bv.x + wv.y * bv.y + wv.z * bv.z + wv.w * bv.w;

        __nv_bfloat162 h01 = __floats2bfloat162_rn(v0, v1);
        __nv_bfloat162 h23 = __floats2bfloat162_rn(v2, v3);
        float2 hf01 = __bfloat1622float2(h01);
        float2 hf23 = __bfloat1622float2(h23);
        __nv_bfloat162 l01 = __floats2bfloat162_rn(v0 - hf01.x, v1 - hf01.y);
        __nv_bfloat162 l23 = __floats2bfloat162_rn(v2 - hf23.x, v3 - hf23.y);
        hdst[c] = make_uint2(*reinterpret_cast<uint32_t*>(&h01),
                             *reinterpret_cast<uint32_t*>(&h23));
        ldst[c] = make_uint2(*reinterpret_cast<uint32_t*>(&l01),
                             *reinterpret_cast<uint32_t*>(&l23));
    }
#pragma unroll
    for (int d = 16; d > 0; d >>= 1) {
        s1 += __shfl_xor_sync(0xffffffffu, s1, d);
        s2 += __shfl_xor_sync(0xffffffffu, s2, d);
    }
    if (lane == 0) {
        g_s1[o] = s1;
        g_s2[o] = s2 + bias[o];
    }
}

// ---------------------------------------------------------------------------
// Stage loader: cp.async one K-chunk (A hi/lo + B hi/lo) into a SMEM stage
// ---------------------------------------------------------------------------
__device__ __forceinline__ void stage_loads(uint32_t stg, int kbase,
                                            int R0, int C0, int tid) {
#pragma unroll
    for (int p = 0; p < 2; p++) {
        int u   = tid + p * 256;    // 512 units: 128 rows x 4 x 16B
        int row = u >> 2;
        int ch  = u & 3;
        uint32_t d = stg + row * ROWB + ch * 16;
        size_t ga = (size_t)(R0 + row) * DIM + kbase + ch * 8;
        size_t gb = (size_t)(C0 + row) * DIM + kbase + ch * 8;
        cpasync16(d + OFF_AH, g_Ahi + ga);
        cpasync16(d + OFF_AL, g_Alo + ga);
        cpasync16(d + OFF_BH, g_Bhi + gb);
        cpasync16(d + OFF_BL, g_Blo + gb);
    }
}

// ---------------------------------------------------------------------------
// Kernel C: split-bf16 HMMA GEMM + LN affine + patch-split epilogue
// 128x128 tile, 8 warps (32x64 each), BK=32, 4-stage cp.async pipeline
// ---------------------------------------------------------------------------
__global__ void __launch_bounds__(256, 1)
gemm_hmma_kernel(float* __restrict__ out) {
    extern __shared__ char smem[];
    const uint32_t sb = smem_u32(smem);
    const int tid = threadIdx.x;
    const int wid = tid >> 5;
    const int lid = tid & 31;
    const int R0 = blockIdx.y * TM;
    const int C0 = blockIdx.x * TN;
    const int Mb = (wid & 3) * 32;   // warp M offset
    const int Nb = (wid >> 2) * 64;  // warp N offset

    float acc[2][8][4];
#pragma unroll
    for (int mt = 0; mt < 2; mt++)
#pragma unroll
        for (int nt = 0; nt < 8; nt++)
#pragma unroll
            for (int k = 0; k < 4; k++) acc[mt][nt][k] = 0.f;

    // prologue: stages 0..2
#pragma unroll
    for (int s = 0; s < STAGES - 1; s++) {
        stage_loads(sb + s * STAGE_BYTES, s * BK, R0, C0, tid);
        cp_commit();
    }

    const int r16 = lid & 15;
    const int kh  = lid >> 4;

    for (int c = 0; c < NCHUNK; c++) {
        int pre = c + STAGES - 1;
        if (pre < NCHUNK)
            stage_loads(sb + (pre & (STAGES - 1)) * STAGE_BYTES, pre * BK, R0, C0, tid);
        cp_commit();
        cp_wait3();
        __syncthreads();

        const uint32_t stg = sb + (c & (STAGES - 1)) * STAGE_BYTES;
#pragma unroll
        for (int ks = 0; ks < 2; ks++) {
            const uint32_t koff = ks * 32 + kh * 16;

            uint32_t ah[2][4], al[2][4];
            uint32_t abase = stg + (Mb + r16) * ROWB + koff;
            ldx4(ah[0], abase + OFF_AH);
            ldx4(ah[1], abase + OFF_AH + 16 * ROWB);
            ldx4(al[0], abase + OFF_AL);
            ldx4(al[1], abase + OFF_AL + 16 * ROWB);

            uint32_t bh[8][2], bl[8][2];
#pragma unroll
            for (int ntp = 0; ntp < 4; ntp++) {
                uint32_t bbase = stg + (Nb + ntp * 16 + r16) * ROWB + koff;
                uint32_t q[4];
                ldx4(q, bbase + OFF_BH);
                bh[2 * ntp][0] = q[0]; bh[2 * ntp][1] = q[2];
                bh[2 * ntp + 1][0] = q[1]; bh[2 * ntp + 1][1] = q[3];
                ldx4(q, bbase + OFF_BL);
                bl[2 * ntp][0] = q[0]; bl[2 * ntp][1] = q[2];
                bl[2 * ntp + 1][0] = q[1]; bl[2 * ntp + 1][1] = q[3];
            }

#pragma unroll
            for (int mt = 0; mt < 2; mt++)
#pragma unroll
                for (int nt = 0; nt < 8; nt++) {
                    mma16816(acc[mt][nt], ah[mt], bh[nt]);
                    mma16816(acc[mt][nt], ah[mt], bl[nt]);
                    mma16816(acc[mt][nt], al[mt], bh[nt]);
                }
        }
        __syncthreads();
    }

    // ---- Epilogue: y = sc*acc - sh*s1[o] + s2[o], patch-split store ----
    const int q  = C0 >> 9;
    const int e1 = q >> 1, e2 = q & 1;
    const int fbase = C0 & (FPN - 1);
    const int colb  = Nb + (lid & 3) * 2;

    float2 s1v[8], s2v[8];
#pragma unroll
    for (int nt = 0; nt < 8; nt++) {
        s1v[nt] = *reinterpret_cast<const float2*>(&g_s1[C0 + colb + nt * 8]);
        s2v[nt] = *reinterpret_cast<const float2*>(&g_s2[C0 + colb + nt * 8]);
    }

#pragma unroll
    for (int mt = 0; mt < 2; mt++) {
#pragma unroll
        for (int rh = 0; rh < 2; rh++) {
            int gr = R0 + Mb + mt * 16 + rh * 8 + (lid >> 2);
            float sc = g_scale[gr];
            float sh = g_shift[gr];
            int bn = gr >> 10;
            int h  = (gr >> 5) & 31;
            int w  = gr & 31;
            float* op = out +
                (((size_t)(bn * 64 + 2 * h + e1) * 64) + (2 * w + e2)) * FPN +
                fbase + colb;
#pragma unroll
            for (int nt = 0; nt < 8; nt++) {
                float2 v;
                v.x = sc * acc[mt][nt][rh * 2]     - sh * s1v[nt].x + s2v[nt].x;
                v.y = sc * acc[mt][nt][rh * 2 + 1] - sh * s1v[nt].y + s2v[nt].y;
                *reinterpret_cast<float2*>(op + nt * 8) = v;
            }
        }
    }
}

// ---------------------------------------------------------------------------
// Launch contract
// ---------------------------------------------------------------------------
extern "C" void kernel_launch(void* const* d_in, const int* in_sizes, int n_in,
                              void* d_out, int out_size) {
    const float* x     = (const float*)d_in[0];
    const float* gamma = (const float*)d_in[1];
    const float* beta  = (const float*)d_in[2];
    const float* Wm    = (const float*)d_in[3];
    const float* bias  = (const float*)d_in[4];
    float* out = (float*)d_out;

    cudaFuncSetAttribute(gemm_hmma_kernel,
                         cudaFuncAttributeMaxDynamicSharedMemorySize, SMEM_TOTAL);

    ln_prep_a_kernel<<<MROWS / 8, 256>>>(x);
    prep_w_kernel<<<NOUT / 8, 256>>>(Wm, gamma, beta, bias);

    dim3 grid(NOUT / TN, MROWS / TM);  // (16, 512)
    gemm_hmma_kernel<<<grid, 256, SMEM_TOTAL>>>(out);
}

// round 7
// speedup vs baseline: 2.6685x; 1.6530x over previous
#include <cuda_runtime.h>
#include <cuda_fp16.h>
#include <cstdint>

// ---------------------------------------------------------------------------
// Problem constants
// ---------------------------------------------------------------------------
#define DIM    1024
#define FPN    512
#define NOUT   2048
#define MROWS  65536            // 16*4*32*32

// GEMM tiling
#define TM 128
#define TN 128
#define BK 32
#define NCHUNK (DIM / BK)       // 32
#define STAGES 3

// SMEM: padded rows of 80B (32 fp16 = 64B data + 16B pad) -> conflict-free ldmatrix
#define ROWB 80
#define ARRB (128 * ROWB)       // 10240 bytes per array per stage
#define OFF_AH 0
#define OFF_AL (1 * ARRB)
#define OFF_BH (2 * ARRB)
#define STAGE_BYTES (3 * ARRB)  // 30720
#define SMEM_TOTAL (STAGES * STAGE_BYTES)  // 92160  -> 2 CTAs/SM

// ---------------------------------------------------------------------------
// Device scratch (device globals; no dynamic allocation allowed)
// ---------------------------------------------------------------------------
__device__ float g_scale[MROWS];                 // rstd
__device__ float g_shift[MROWS];                 // rstd * mu
__device__ __half g_Ahi[(size_t)MROWS * DIM];    // 128 MB
__device__ __half g_Alo[(size_t)MROWS * DIM];    // 128 MB
__device__ __half g_Bh[(size_t)NOUT * DIM];      // 4 MB
__device__ float g_s1[NOUT];
__device__ float g_s2[NOUT];

// ---------------------------------------------------------------------------
// PTX helpers (base PTX, family-generic sm_103 safe)
// ---------------------------------------------------------------------------
__device__ __forceinline__ uint32_t smem_u32(const void* p) {
    uint32_t a;
    asm("{ .reg .u64 t; cvta.to.shared.u64 t, %1; cvt.u32.u64 %0, t; }"
        : "=r"(a) : "l"(p));
    return a;
}
__device__ __forceinline__ void cpasync16(uint32_t dst, const void* src) {
    asm volatile("cp.async.cg.shared.global [%0], [%1], 16;"
                 :: "r"(dst), "l"(src));
}
__device__ __forceinline__ void cp_commit() {
    asm volatile("cp.async.commit_group;");
}
__device__ __forceinline__ void cp_wait2() {
    asm volatile("cp.async.wait_group 2;");
}
__device__ __forceinline__ void ldx4(uint32_t* r, uint32_t addr) {
    asm volatile("ldmatrix.sync.aligned.m8n8.x4.shared.b16 {%0,%1,%2,%3}, [%4];"
                 : "=r"(r[0]), "=r"(r[1]), "=r"(r[2]), "=r"(r[3]) : "r"(addr));
}
__device__ __forceinline__ void mma16816(float* d, const uint32_t* a,
                                         const uint32_t* b) {
    asm volatile(
        "mma.sync.aligned.m16n8k16.row.col.f32.f16.f16.f32 "
        "{%0,%1,%2,%3}, {%4,%5,%6,%7}, {%8,%9}, {%0,%1,%2,%3};"
        : "+f"(d[0]), "+f"(d[1]), "+f"(d[2]), "+f"(d[3])
        : "r"(a[0]), "r"(a[1]), "r"(a[2]), "r"(a[3]), "r"(b[0]), "r"(b[1]));
}

// ---------------------------------------------------------------------------
// Kernel A: LN stats + fp32 -> fp16 hi/lo split of x (one warp per row)
// ---------------------------------------------------------------------------
__global__ void ln_prep_a_kernel(const float* __restrict__ x) {
    int gw   = (blockIdx.x * blockDim.x + threadIdx.x) >> 5;
    int lane = threadIdx.x & 31;
    const float4* row = reinterpret_cast<const float4*>(x) + (size_t)gw * (DIM / 4);

    float4 v[8];
    float s = 0.f;
#pragma unroll
    for (int i = 0; i < 8; i++) {
        v[i] = row[lane + i * 32];
        s += v[i].x + v[i].y + v[i].z + v[i].w;
    }
#pragma unroll
    for (int o = 16; o > 0; o >>= 1) s += __shfl_xor_sync(0xffffffffu, s, o);
    float mu = s * (1.f / DIM);

    float q = 0.f;
#pragma unroll
    for (int i = 0; i < 8; i++) {
        float a = v[i].x - mu, b = v[i].y - mu, c = v[i].z - mu, d = v[i].w - mu;
        q += a * a + b * b + c * c + d * d;
    }
#pragma unroll
    for (int o = 16; o > 0; o >>= 1) q += __shfl_xor_sync(0xffffffffu, q, o);

    if (lane == 0) {
        float rstd = rsqrtf(q * (1.f / DIM) + 1e-5f);
        g_scale[gw] = rstd;
        g_shift[gw] = rstd * mu;
    }

    uint2* hdst = reinterpret_cast<uint2*>(g_Ahi + (size_t)gw * DIM);
    uint2* ldst = reinterpret_cast<uint2*>(g_Alo + (size_t)gw * DIM);
#pragma unroll
    for (int i = 0; i < 8; i++) {
        int idx = lane + i * 32;
        float f0 = v[i].x, f1 = v[i].y, f2 = v[i].z, f3 = v[i].w;
        __half2 h01 = __float22half2_rn(make_float2(f0, f1));
        __half2 h23 = __float22half2_rn(make_float2(f2, f3));
        float2 hf01 = __half22float2(h01);
        float2 hf23 = __half22float2(h23);
        __half2 l01 = __float22half2_rn(make_float2(f0 - hf01.x, f1 - hf01.y));
        __half2 l23 = __float22half2_rn(make_float2(f2 - hf23.x, f3 - hf23.y));
        hdst[idx] = make_uint2(*reinterpret_cast<uint32_t*>(&h01),
                               *reinterpret_cast<uint32_t*>(&h23));
        ldst[idx] = make_uint2(*reinterpret_cast<uint32_t*>(&l01),
                               *reinterpret_cast<uint32_t*>(&l23));
    }
}

// ---------------------------------------------------------------------------
// Kernel B: W' = gamma*W as fp16 (hi only); s1 = sum W', s2 = beta.W + bias
// ---------------------------------------------------------------------------
__global__ void prep_w_kernel(const float* __restrict__ Wm,
                              const float* __restrict__ gamma,
                              const float* __restrict__ beta,
                              const float* __restrict__ bias) {
    int o    = (blockIdx.x * blockDim.x + threadIdx.x) >> 5;
    int lane = threadIdx.x & 31;
    if (o >= NOUT) return;

    const float4* wr = reinterpret_cast<const float4*>(Wm) + (size_t)o * (DIM / 4);
    const float4* g4 = reinterpret_cast<const float4*>(gamma);
    const float4* b4 = reinterpret_cast<const float4*>(beta);
    uint2* hdst = reinterpret_cast<uint2*>(g_Bh + (size_t)o * DIM);

    float s1 = 0.f, s2 = 0.f;
#pragma unroll
    for (int i = 0; i < 8; i++) {
        int c = lane + i * 32;
        float4 wv = wr[c], gv = g4[c], bv = b4[c];
        float v0 = wv.x * gv.x, v1 = wv.y * gv.y, v2 = wv.z * gv.z, v3 = wv.w * gv.w;
        s1 += v0 + v1 + v2 + v3;
        s2 += wv.x * bv.x + wv.y * bv.y + wv.z * bv.z + wv.w * bv.w;

        __half2 h01 = __float22half2_rn(make_float2(v0, v1));
        __half2 h23 = __float22half2_rn(make_float2(v2, v3));
        hdst[c] = make_uint2(*reinterpret_cast<uint32_t*>(&h01),
                             *reinterpret_cast<uint32_t*>(&h23));
    }
#pragma unroll
    for (int d = 16; d > 0; d >>= 1) {
        s1 += __shfl_xor_sync(0xffffffffu, s1, d);
        s2 += __shfl_xor_sync(0xffffffffu, s2, d);
    }
    if (lane == 0) {
        g_s1[o] = s1;
        g_s2[o] = s2 + bias[o];
    }
}

// ---------------------------------------------------------------------------
// Stage loader: cp.async one K-chunk (A hi/lo + B hi) into a SMEM stage
// ---------------------------------------------------------------------------
__device__ __forceinline__ void stage_loads(uint32_t stg, int kbase,
                                            int R0, int C0, int tid) {
#pragma unroll
    for (int p = 0; p < 2; p++) {
        int u   = tid + p * 256;    // 512 units: 128 rows x 4 x 16B
        int row = u >> 2;
        int ch  = u & 3;
        uint32_t d = stg + row * ROWB + ch * 16;
        size_t ga = (size_t)(R0 + row) * DIM + kbase + ch * 8;
        size_t gb = (size_t)(C0 + row) * DIM + kbase + ch * 8;
        cpasync16(d + OFF_AH, g_Ahi + ga);
        cpasync16(d + OFF_AL, g_Alo + ga);
        cpasync16(d + OFF_BH, g_Bh + gb);
    }
}

// ---------------------------------------------------------------------------
// Kernel C: split-fp16 HMMA GEMM (2 products) + LN affine + patch-split
// 128x128 tile, 8 warps (32x64 each), BK=32, 3-stage cp.async, 2 CTAs/SM
// ---------------------------------------------------------------------------
__global__ void __launch_bounds__(256, 2)
gemm_hmma_kernel(float* __restrict__ out) {
    extern __shared__ char smem[];
    const uint32_t sb = smem_u32(smem);
    const int tid = threadIdx.x;
    const int wid = tid >> 5;
    const int lid = tid & 31;
    const int R0 = blockIdx.y * TM;
    const int C0 = blockIdx.x * TN;
    const int Mb = (wid & 3) * 32;   // warp M offset
    const int Nb = (wid >> 2) * 64;  // warp N offset

    float acc[2][8][4];
#pragma unroll
    for (int mt = 0; mt < 2; mt++)
#pragma unroll
        for (int nt = 0; nt < 8; nt++)
#pragma unroll
            for (int k = 0; k < 4; k++) acc[mt][nt][k] = 0.f;

    // prologue: stages 0..1 hold chunks 0..1
#pragma unroll
    for (int s = 0; s < STAGES - 1; s++) {
        stage_loads(sb + s * STAGE_BYTES, s * BK, R0, C0, tid);
        cp_commit();
    }

    const int r16 = lid & 15;
    const int kh  = lid >> 4;

    // FIXED rotation: compute stage cur == c % 3; prefetch stage pres == (c+2) % 3.
    int cur = 0, pres = STAGES - 1;
    for (int c = 0; c < NCHUNK; c++) {
        int pre = c + STAGES - 1;
        if (pre < NCHUNK)
            stage_loads(sb + pres * STAGE_BYTES, pre * BK, R0, C0, tid);
        cp_commit();
        cp_wait2();
        __syncthreads();

        const uint32_t stg = sb + cur * STAGE_BYTES;
#pragma unroll
        for (int ks = 0; ks < 2; ks++) {
            const uint32_t koff = ks * 32 + kh * 16;

            uint32_t ah[2][4], al[2][4];
            uint32_t abase = stg + (Mb + r16) * ROWB + koff;
            ldx4(ah[0], abase + OFF_AH);
            ldx4(ah[1], abase + OFF_AH + 16 * ROWB);
            ldx4(al[0], abase + OFF_AL);
            ldx4(al[1], abase + OFF_AL + 16 * ROWB);

            // B in two groups of 4 n-tiles (lower register pressure)
#pragma unroll
            for (int g = 0; g < 2; g++) {
                uint32_t bbase = stg + (Nb + g * 32 + r16) * ROWB + koff + OFF_BH;
                uint32_t q0[4], q1[4];
                ldx4(q0, bbase);
                ldx4(q1, bbase + 16 * ROWB);
                uint32_t bh[4][2];
                bh[0][0] = q0[0]; bh[0][1] = q0[2];
                bh[1][0] = q0[1]; bh[1][1] = q0[3];
                bh[2][0] = q1[0]; bh[2][1] = q1[2];
                bh[3][0] = q1[1]; bh[3][1] = q1[3];
#pragma unroll
                for (int mt = 0; mt < 2; mt++)
#pragma unroll
                    for (int j = 0; j < 4; j++) {
                        mma16816(acc[mt][g * 4 + j], ah[mt], bh[j]);
                        mma16816(acc[mt][g * 4 + j], al[mt], bh[j]);
                    }
            }
        }
        __syncthreads();

        cur  = (cur  + 1 == STAGES) ? 0 : cur  + 1;
        pres = (pres + 1 == STAGES) ? 0 : pres + 1;
    }

    // ---- Epilogue: y = sc*acc - sh*s1[o] + s2[o], patch-split store ----
    const int q  = C0 >> 9;
    const int e1 = q >> 1, e2 = q & 1;
    const int fbase = C0 & (FPN - 1);
    const int colb  = Nb + (lid & 3) * 2;

    float2 s1v[8], s2v[8];
#pragma unroll
    for (int nt = 0; nt < 8; nt++) {
        s1v[nt] = *reinterpret_cast<const float2*>(&g_s1[C0 + colb + nt * 8]);
        s2v[nt] = *reinterpret_cast<const float2*>(&g_s2[C0 + colb + nt * 8]);
    }

#pragma unroll
    for (int mt = 0; mt < 2; mt++) {
#pragma unroll
        for (int rh = 0; rh < 2; rh++) {
            int gr = R0 + Mb + mt * 16 + rh * 8 + (lid >> 2);
            float sc = g_scale[gr];
            float sh = g_shift[gr];
            int bn = gr >> 10;
            int h  = (gr >> 5) & 31;
            int w  = gr & 31;
            float* op = out +
                (((size_t)(bn * 64 + 2 * h + e1) * 64) + (2 * w + e2)) * FPN +
                fbase + colb;
#pragma unroll
            for (int nt = 0; nt < 8; nt++) {
                float2 v;
                v.x = sc * acc[mt][nt][rh * 2]     - sh * s1v[nt].x + s2v[nt].x;
                v.y = sc * acc[mt][nt][rh * 2 + 1] - sh * s1v[nt].y + s2v[nt].y;
                *reinterpret_cast<float2*>(op + nt * 8) = v;
            }
        }
    }
}

// ---------------------------------------------------------------------------
// Launch contract
// ---------------------------------------------------------------------------
extern "C" void kernel_launch(void* const* d_in, const int* in_sizes, int n_in,
                              void* d_out, int out_size) {
    const float* x     = (const float*)d_in[0];
    const float* gamma = (const float*)d_in[1];
    const float* beta  = (const float*)d_in[2];
    const float* Wm    = (const float*)d_in[3];
    const float* bias  = (const float*)d_in[4];
    float* out = (float*)d_out;

    cudaFuncSetAttribute(gemm_hmma_kernel,
                         cudaFuncAttributeMaxDynamicSharedMemorySize, SMEM_TOTAL);

    ln_prep_a_kernel<<<MROWS / 8, 256>>>(x);
    prep_w_kernel<<<NOUT / 8, 256>>>(Wm, gamma, beta, bias);

    dim3 grid(NOUT / TN, MROWS / TM);  // (16, 512)
    gemm_hmma_kernel<<<grid, 256, SMEM_TOTAL>>>(out);
}

// round 8
// speedup vs baseline: 4.4595x; 1.6712x over previous
#include <cuda_runtime.h>
#include <cuda_fp16.h>
#include <cstdint>

// ---------------------------------------------------------------------------
// Problem constants
// ---------------------------------------------------------------------------
#define DIM    1024
#define FPN    512
#define NOUT   2048
#define MROWS  65536            // 16*4*32*32

// GEMM tiling
#define TM 128
#define TN 128
#define BK 32
#define NCHUNK (DIM / BK)       // 32
#define STAGES 4                // power of two -> & (STAGES-1) indexing

// SMEM: padded rows of 80B (32 fp16 = 64B data + 16B pad) -> conflict-free ldmatrix
#define ROWB 80
#define ARRB (128 * ROWB)       // 10240 bytes per array per stage
#define OFF_AH 0
#define OFF_BH (1 * ARRB)
#define STAGE_BYTES (2 * ARRB)  // 20480
#define SMEM_TOTAL (STAGES * STAGE_BYTES)  // 81920 -> 2 CTAs/SM

// ---------------------------------------------------------------------------
// Device scratch (device globals; no dynamic allocation allowed)
// ---------------------------------------------------------------------------
__device__ float g_scale[MROWS];                 // rstd
__device__ float g_shift[MROWS];                 // rstd * mu
__device__ __half g_Ah[(size_t)MROWS * DIM];     // 128 MB
__device__ __half g_Bh[(size_t)NOUT * DIM];      // 4 MB
__device__ float g_s1[NOUT];
__device__ float g_s2[NOUT];

// ---------------------------------------------------------------------------
// PTX helpers (base PTX, family-generic sm_103 safe)
// ---------------------------------------------------------------------------
__device__ __forceinline__ uint32_t smem_u32(const void* p) {
    uint32_t a;
    asm("{ .reg .u64 t; cvta.to.shared.u64 t, %1; cvt.u32.u64 %0, t; }"
        : "=r"(a) : "l"(p));
    return a;
}
__device__ __forceinline__ void cpasync16(uint32_t dst, const void* src) {
    asm volatile("cp.async.cg.shared.global [%0], [%1], 16;"
                 :: "r"(dst), "l"(src));
}
__device__ __forceinline__ void cp_commit() {
    asm volatile("cp.async.commit_group;");
}
__device__ __forceinline__ void cp_wait3() {
    asm volatile("cp.async.wait_group 3;");
}
__device__ __forceinline__ void ldx4(uint32_t* r, uint32_t addr) {
    asm volatile("ldmatrix.sync.aligned.m8n8.x4.shared.b16 {%0,%1,%2,%3}, [%4];"
                 : "=r"(r[0]), "=r"(r[1]), "=r"(r[2]), "=r"(r[3]) : "r"(addr));
}
__device__ __forceinline__ void mma16816(float* d, const uint32_t* a,
                                         const uint32_t* b) {
    asm volatile(
        "mma.sync.aligned.m16n8k16.row.col.f32.f16.f16.f32 "
        "{%0,%1,%2,%3}, {%4,%5,%6,%7}, {%8,%9}, {%0,%1,%2,%3};"
        : "+f"(d[0]), "+f"(d[1]), "+f"(d[2]), "+f"(d[3])
        : "r"(a[0]), "r"(a[1]), "r"(a[2]), "r"(a[3]), "r"(b[0]), "r"(b[1]));
}

// ---------------------------------------------------------------------------
// Kernel A: LN stats + fp32 -> fp16 conversion of x (one warp per row)
// ---------------------------------------------------------------------------
__global__ void ln_prep_a_kernel(const float* __restrict__ x) {
    int gw   = (blockIdx.x * blockDim.x + threadIdx.x) >> 5;
    int lane = threadIdx.x & 31;
    const float4* row = reinterpret_cast<const float4*>(x) + (size_t)gw * (DIM / 4);

    float4 v[8];
    float s = 0.f;
#pragma unroll
    for (int i = 0; i < 8; i++) {
        v[i] = row[lane + i * 32];
        s += v[i].x + v[i].y + v[i].z + v[i].w;
    }
#pragma unroll
    for (int o = 16; o > 0; o >>= 1) s += __shfl_xor_sync(0xffffffffu, s, o);
    float mu = s * (1.f / DIM);

    float q = 0.f;
#pragma unroll
    for (int i = 0; i < 8; i++) {
        float a = v[i].x - mu, b = v[i].y - mu, c = v[i].z - mu, d = v[i].w - mu;
        q += a * a + b * b + c * c + d * d;
    }
#pragma unroll
    for (int o = 16; o > 0; o >>= 1) q += __shfl_xor_sync(0xffffffffu, q, o);

    if (lane == 0) {
        float rstd = rsqrtf(q * (1.f / DIM) + 1e-5f);
        g_scale[gw] = rstd;
        g_shift[gw] = rstd * mu;
    }

    uint2* hdst = reinterpret_cast<uint2*>(g_Ah + (size_t)gw * DIM);
#pragma unroll
    for (int i = 0; i < 8; i++) {
        int idx = lane + i * 32;
        __half2 h01 = __float22half2_rn(make_float2(v[i].x, v[i].y));
        __half2 h23 = __float22half2_rn(make_float2(v[i].z, v[i].w));
        hdst[idx] = make_uint2(*reinterpret_cast<uint32_t*>(&h01),
                               *reinterpret_cast<uint32_t*>(&h23));
    }
}

// ---------------------------------------------------------------------------
// Kernel B: W' = gamma*W as fp16; s1 = sum W', s2 = beta.W + bias
// ---------------------------------------------------------------------------
__global__ void prep_w_kernel(const float* __restrict__ Wm,
                              const float* __restrict__ gamma,
                              const float* __restrict__ beta,
                              const float* __restrict__ bias) {
    int o    = (blockIdx.x * blockDim.x + threadIdx.x) >> 5;
    int lane = threadIdx.x & 31;
    if (o >= NOUT) return;

    const float4* wr = reinterpret_cast<const float4*>(Wm) + (size_t)o * (DIM / 4);
    const float4* g4 = reinterpret_cast<const float4*>(gamma);
    const float4* b4 = reinterpret_cast<const float4*>(beta);
    uint2* hdst = reinterpret_cast<uint2*>(g_Bh + (size_t)o * DIM);

    float s1 = 0.f, s2 = 0.f;
#pragma unroll
    for (int i = 0; i < 8; i++) {
        int c = lane + i * 32;
        float4 wv = wr[c], gv = g4[c], bv = b4[c];
        float v0 = wv.x * gv.x, v1 = wv.y * gv.y, v2 = wv.z * gv.z, v3 = wv.w * gv.w;
        s1 += v0 + v1 + v2 + v3;
        s2 += wv.x * bv.x + wv.y * bv.y + wv.z * bv.z + wv.w * bv.w;

        __half2 h01 = __float22half2_rn(make_float2(v0, v1));
        __half2 h23 = __float22half2_rn(make_float2(v2, v3));
        hdst[c] = make_uint2(*reinterpret_cast<uint32_t*>(&h01),
                             *reinterpret_cast<uint32_t*>(&h23));
    }
#pragma unroll
    for (int d = 16; d > 0; d >>= 1) {
        s1 += __shfl_xor_sync(0xffffffffu, s1, d);
        s2 += __shfl_xor_sync(0xffffffffu, s2, d);
    }
    if (lane == 0) {
        g_s1[o] = s1;
        g_s2[o] = s2 + bias[o];
    }
}

// ---------------------------------------------------------------------------
// Stage loader: cp.async one K-chunk (A + B) into a SMEM stage
// ---------------------------------------------------------------------------
__device__ __forceinline__ void stage_loads(uint32_t stg, int kbase,
                                            int R0, int C0, int tid) {
#pragma unroll
    for (int p = 0; p < 2; p++) {
        int u   = tid + p * 256;    // 512 units: 128 rows x 4 x 16B
        int row = u >> 2;
        int ch  = u & 3;
        uint32_t d = stg + row * ROWB + ch * 16;
        size_t ga = (size_t)(R0 + row) * DIM + kbase + ch * 8;
        size_t gb = (size_t)(C0 + row) * DIM + kbase + ch * 8;
        cpasync16(d + OFF_AH, g_Ah + ga);
        cpasync16(d + OFF_BH, g_Bh + gb);
    }
}

// ---------------------------------------------------------------------------
// Kernel C: fp16 HMMA GEMM (single product) + LN affine + patch-split
// 128x128 tile, 8 warps (32x64 each), BK=32, 4-stage cp.async, 2 CTAs/SM
// ---------------------------------------------------------------------------
__global__ void __launch_bounds__(256, 2)
gemm_hmma_kernel(float* __restrict__ out) {
    extern __shared__ char smem[];
    const uint32_t sb = smem_u32(smem);
    const int tid = threadIdx.x;
    const int wid = tid >> 5;
    const int lid = tid & 31;
    const int R0 = blockIdx.y * TM;
    const int C0 = blockIdx.x * TN;
    const int Mb = (wid & 3) * 32;   // warp M offset
    const int Nb = (wid >> 2) * 64;  // warp N offset

    float acc[2][8][4];
#pragma unroll
    for (int mt = 0; mt < 2; mt++)
#pragma unroll
        for (int nt = 0; nt < 8; nt++)
#pragma unroll
            for (int k = 0; k < 4; k++) acc[mt][nt][k] = 0.f;

    // prologue: stages 0..2 hold chunks 0..2
#pragma unroll
    for (int s = 0; s < STAGES - 1; s++) {
        stage_loads(sb + s * STAGE_BYTES, s * BK, R0, C0, tid);
        cp_commit();
    }

    const int r16 = lid & 15;
    const int kh  = lid >> 4;

    for (int c = 0; c < NCHUNK; c++) {
        int pre = c + STAGES - 1;
        if (pre < NCHUNK)
            stage_loads(sb + (pre & (STAGES - 1)) * STAGE_BYTES, pre * BK, R0, C0, tid);
        cp_commit();
        cp_wait3();
        __syncthreads();

        const uint32_t stg = sb + (c & (STAGES - 1)) * STAGE_BYTES;
#pragma unroll
        for (int ks = 0; ks < 2; ks++) {
            const uint32_t koff = ks * 32 + kh * 16;

            uint32_t ah[2][4];
            uint32_t abase = stg + (Mb + r16) * ROWB + koff;
            ldx4(ah[0], abase + OFF_AH);
            ldx4(ah[1], abase + OFF_AH + 16 * ROWB);

            // B in two groups of 4 n-tiles (lower register pressure)
#pragma unroll
            for (int g = 0; g < 2; g++) {
                uint32_t bbase = stg + (Nb + g * 32 + r16) * ROWB + koff + OFF_BH;
                uint32_t q0[4], q1[4];
                ldx4(q0, bbase);
                ldx4(q1, bbase + 16 * ROWB);
                uint32_t bh[4][2];
                bh[0][0] = q0[0]; bh[0][1] = q0[2];
                bh[1][0] = q0[1]; bh[1][1] = q0[3];
                bh[2][0] = q1[0]; bh[2][1] = q1[2];
                bh[3][0] = q1[1]; bh[3][1] = q1[3];
#pragma unroll
                for (int mt = 0; mt < 2; mt++)
#pragma unroll
                    for (int j = 0; j < 4; j++)
                        mma16816(acc[mt][g * 4 + j], ah[mt], bh[j]);
            }
        }
        __syncthreads();
    }

    // ---- Epilogue: y = sc*acc - sh*s1[o] + s2[o], patch-split store ----
    const int q  = C0 >> 9;
    const int e1 = q >> 1, e2 = q & 1;
    const int fbase = C0 & (FPN - 1);
    const int colb  = Nb + (lid & 3) * 2;

    float2 s1v[8], s2v[8];
#pragma unroll
    for (int nt = 0; nt < 8; nt++) {
        s1v[nt] = *reinterpret_cast<const float2*>(&g_s1[C0 + colb + nt * 8]);
        s2v[nt] = *reinterpret_cast<const float2*>(&g_s2[C0 + colb + nt * 8]);
    }

#pragma unroll
    for (int mt = 0; mt < 2; mt++) {
#pragma unroll
        for (int rh = 0; rh < 2; rh++) {
            int gr = R0 + Mb + mt * 16 + rh * 8 + (lid >> 2);
            float sc = g_scale[gr];
            float sh = g_shift[gr];
            int bn = gr >> 10;
            int h  = (gr >> 5) & 31;
            int w  = gr & 31;
            float* op = out +
                (((size_t)(bn * 64 + 2 * h + e1) * 64) + (2 * w + e2)) * FPN +
                fbase + colb;
#pragma unroll
            for (int nt = 0; nt < 8; nt++) {
                float2 v;
                v.x = sc * acc[mt][nt][rh * 2]     - sh * s1v[nt].x + s2v[nt].x;
                v.y = sc * acc[mt][nt][rh * 2 + 1] - sh * s1v[nt].y + s2v[nt].y;
                *reinterpret_cast<float2*>(op + nt * 8) = v;
            }
        }
    }
}

// ---------------------------------------------------------------------------
// Launch contract
// ---------------------------------------------------------------------------
extern "C" void kernel_launch(void* const* d_in, const int* in_sizes, int n_in,
                              void* d_out, int out_size) {
    const float* x     = (const float*)d_in[0];
    const float* gamma = (const float*)d_in[1];
    const float* beta  = (const float*)d_in[2];
    const float* Wm    = (const float*)d_in[3];
    const float* bias  = (const float*)d_in[4];
    float* out = (float*)d_out;

    cudaFuncSetAttribute(gemm_hmma_kernel,
                         cudaFuncAttributeMaxDynamicSharedMemorySize, SMEM_TOTAL);

    ln_prep_a_kernel<<<MROWS / 8, 256>>>(x);
    prep_w_kernel<<<NOUT / 8, 256>>>(Wm, gamma, beta, bias);

    dim3 grid(NOUT / TN, MROWS / TM);  // (16, 512)
    gemm_hmma_kernel<<<grid, 256, SMEM_TOTAL>>>(out);
}